// round 2
// baseline (speedup 1.0000x reference)
#include <cuda_runtime.h>
#include <math.h>

// Problem constants
#define BB 4
#define TT 512
#define MM 16
#define DD 128
#define PP 128
#define HH 4
#define EE 32           // head dim
#define TWOE 64         // concat(q, q_t) head dim

// Scratch (allowed: __device__ globals, no runtime alloc)
__device__ float g_QC[(size_t)BB * MM * HH * TT * TWOE];  // [b][m][h][t][64] : q | q_t
__device__ float g_KC[(size_t)BB * MM * HH * TT * TWOE];  // [b][m][h][t][64] : k | k_t
__device__ float g_V [(size_t)BB * MM * HH * TT * EE];    // [b][m][h][t][32]
__device__ int   g_len[BB];

// ---------------------------------------------------------------------------
// K0: derive per-batch lengths from mask, robust to bool/int32/float32 storage.
// mask[b,t,m] = (t < length[b]) so element (b,t,0) nonzero <=> t < length[b].
// Detection: elements 0 and 1 (t=0 -> true). bool: bytes 1,1. int32 one: 1,0.
// float32 1.0f: 0x00,0x00,0x80,0x3F -> byte0=0. So (b0==1 && b1==1) <=> 1-byte.
// ---------------------------------------------------------------------------
__global__ void lengths_kernel(const unsigned char* __restrict__ mask) {
    __shared__ int cnt;
    int tid = threadIdx.x;  // 512 threads
    unsigned char b0 = mask[0], b1 = mask[1];
    bool one_byte = (b0 == 1 && b1 == 1);
    for (int b = 0; b < BB; b++) {
        if (tid == 0) cnt = 0;
        __syncthreads();
        size_t ei = ((size_t)b * TT + tid) * MM;  // element index of (b, t=tid, m=0)
        bool v;
        if (one_byte) {
            v = mask[ei] != 0;
        } else {
            const unsigned int* m32 = (const unsigned int*)mask;
            v = m32[ei] != 0u;  // works for int32 1 and float32 1.0f bit patterns
        }
        unsigned bal = __ballot_sync(0xffffffffu, v);
        if ((tid & 31) == 0) atomicAdd(&cnt, __popc(bal));
        __syncthreads();
        if (tid == 0) g_len[b] = cnt;
        __syncthreads();
    }
}

// ---------------------------------------------------------------------------
// K1: projections. Block = (m, 32 consecutive bt rows) x all 128 p, K=D=128.
// 5 matrices streamed sequentially reusing the input tiles in smem.
// Ws is stored transposed [d][p] (unpadded): compute-side LDS.128 of 4
// consecutive p per lane is phase-conflict-free.
// ---------------------------------------------------------------------------
__global__ void __launch_bounds__(128) proj_kernel(
    const float* __restrict__ inp, const float* __restrict__ pos,
    const float* __restrict__ wq, const float* __restrict__ bq,
    const float* __restrict__ wk, const float* __restrict__ bk,
    const float* __restrict__ wv, const float* __restrict__ bv,
    const float* __restrict__ wqt, const float* __restrict__ bqt,
    const float* __restrict__ wkt, const float* __restrict__ bkt)
{
    __shared__ float Xs[32][DD];   // inp rows   (16 KB)
    __shared__ float Ps[32][DD];   // pos rows   (16 KB)
    __shared__ float Ws[32][PP];   // W chunk, transposed [d_local][p] (16 KB)

    const int m   = blockIdx.x;
    const int bt0 = blockIdx.y * 32;
    const int tid = threadIdx.x;   // 128

    // Load input tiles once (coalesced: 8 consecutive threads read 128B rows)
    #pragma unroll
    for (int it = 0; it < 8; it++) {
        int idx = it * 128 + tid;       // float4 index, 1024 total per tile
        int r = idx >> 5, c4 = idx & 31;
        int bt = bt0 + r;
        float4 vx = *(const float4*)&inp[((size_t)bt * MM + m) * DD + c4 * 4];
        *(float4*)&Xs[r][c4 * 4] = vx;
        float4 vp = *(const float4*)&pos[(size_t)bt * DD + c4 * 4];
        *(float4*)&Ps[r][c4 * 4] = vp;
    }

    const int c0 = (tid & 31) * 4;   // 4 output columns (p)
    const int r0 = (tid >> 5) * 8;   // 8 rows
    const int h  = c0 >> 5;
    const int e0 = c0 & 31;

    const float* Wm[5] = {wq, wk, wv, wqt, wkt};
    const float* Bm[5] = {bq, bk, bv, bqt, bkt};

    #pragma unroll 1
    for (int mat = 0; mat < 5; mat++) {
        const float* W = Wm[mat] + (size_t)m * PP * DD;
        const bool usePos = (mat >= 3);
        float acc[8][4];
        #pragma unroll
        for (int r = 0; r < 8; r++)
            #pragma unroll
            for (int j = 0; j < 4; j++) acc[r][j] = 0.f;

        #pragma unroll 1
        for (int dc = 0; dc < 4; dc++) {            // 4 chunks of 32 d
            __syncthreads();                        // previous Ws consumers done
            #pragma unroll
            for (int it = 0; it < 8; it++) {
                int idx = it * 128 + tid;           // 1024 float4s
                int p = idx >> 3, c4 = idx & 7;
                float4 w4 = *(const float4*)&W[(size_t)p * DD + dc * 32 + c4 * 4];
                Ws[c4 * 4 + 0][p] = w4.x;
                Ws[c4 * 4 + 1][p] = w4.y;
                Ws[c4 * 4 + 2][p] = w4.z;
                Ws[c4 * 4 + 3][p] = w4.w;
            }
            __syncthreads();
            const float (*X)[DD] = usePos ? Ps : Xs;
            #pragma unroll 8
            for (int dd = 0; dd < 32; dd++) {
                int d = dc * 32 + dd;
                float4 w = *(const float4*)&Ws[dd][c0];
                float x[8];
                #pragma unroll
                for (int r = 0; r < 8; r++) x[r] = X[r0 + r][d];
                #pragma unroll
                for (int r = 0; r < 8; r++) {
                    acc[r][0] += x[r] * w.x;
                    acc[r][1] += x[r] * w.y;
                    acc[r][2] += x[r] * w.z;
                    acc[r][3] += x[r] * w.w;
                }
            }
        }

        float bias[4];
        #pragma unroll
        for (int j = 0; j < 4; j++) bias[j] = Bm[mat][m * PP + c0 + j];

        #pragma unroll
        for (int r = 0; r < 8; r++) {
            int bt = bt0 + r0 + r;
            int b = bt >> 9, t = bt & (TT - 1);
            size_t row = (((size_t)(b * MM + m) * HH + h) * TT + t);
            float4 v = make_float4(acc[r][0] + bias[0], acc[r][1] + bias[1],
                                   acc[r][2] + bias[2], acc[r][3] + bias[3]);
            switch (mat) {
                case 0: *(float4*)&g_QC[row * TWOE + e0]      = v; break;
                case 1: *(float4*)&g_KC[row * TWOE + e0]      = v; break;
                case 2: *(float4*)&g_V [row * EE   + e0]      = v; break;
                case 3: *(float4*)&g_QC[row * TWOE + 32 + e0] = v; break;
                case 4: *(float4*)&g_KC[row * TWOE + 32 + e0] = v; break;
            }
        }
    }
}

// ---------------------------------------------------------------------------
// K2: flash attention. Block = (b,m,h, 128-query tile). One thread per query,
// q row (64) in registers, K/V tiles in smem (all reads warp-broadcast).
// score = dot64(qc, kc) * 1/(2*sqrt(32)); causal + length masking; online
// softmax in chunks of 8 keys (one rescale per chunk at most).
// ---------------------------------------------------------------------------
__global__ void __launch_bounds__(128) attn_kernel(float* __restrict__ out) {
    __shared__ float Ks[128][TWOE];  // 32 KB
    __shared__ float Vs[128][EE];    // 16 KB

    const int qt  = blockIdx.x;            // query tile 0..3
    const int h   = blockIdx.y;
    const int bm  = blockIdx.z;
    const int b   = bm / MM, m = bm % MM;
    const int tid = threadIdx.x;           // 128
    const int t   = qt * 128 + tid;
    const float scale = 0.08838834764831845f;  // 1/(2*sqrt(32))

    const size_t head = ((size_t)(b * MM + m) * HH + h) * TT;
    const float* Kbase = &g_KC[head * TWOE];
    const float* Vbase = &g_V [head * EE];

    float q[TWOE];
    {
        const float* qc = &g_QC[(head + t) * TWOE];
        #pragma unroll
        for (int j = 0; j < TWOE; j += 4) {
            float4 v = *(const float4*)&qc[j];
            q[j] = v.x; q[j + 1] = v.y; q[j + 2] = v.z; q[j + 3] = v.w;
        }
    }

    const int len = g_len[b];
    float mi = -INFINITY, li = 0.f;
    float o[EE];
    #pragma unroll
    for (int e = 0; e < EE; e++) o[e] = 0.f;

    int s_hi = qt * 128 + 127;
    if (s_hi > len - 1) s_hi = len - 1;   // len >= 1 always (T/2 minimum)
    const int ntiles = s_hi / 128 + 1;

    for (int ktile = 0; ktile < ntiles; ktile++) {
        const int s0 = ktile * 128;
        __syncthreads();
        #pragma unroll
        for (int it = 0; it < 16; it++) {           // K tile: 2048 float4
            int idx = it * 128 + tid;
            int r = idx >> 4, c = idx & 15;
            *(float4*)&Ks[r][c * 4] = *(const float4*)&Kbase[(size_t)(s0 + r) * TWOE + c * 4];
        }
        #pragma unroll
        for (int it = 0; it < 8; it++) {            // V tile: 1024 float4
            int idx = it * 128 + tid;
            int r = idx >> 3, c = idx & 7;
            *(float4*)&Vs[r][c * 4] = *(const float4*)&Vbase[(size_t)(s0 + r) * EE + c * 4];
        }
        __syncthreads();

        int s_cnt = len - s0; if (s_cnt > 128) s_cnt = 128;   // uniform per block

        for (int sc = 0; sc < s_cnt; sc += 8) {
            float x[8];
            #pragma unroll
            for (int c = 0; c < 8; c++) {
                const int s = sc + c;
                float d0 = 0.f, d1 = 0.f, d2 = 0.f, d3 = 0.f;
                #pragma unroll
                for (int j = 0; j < TWOE; j += 4) {
                    float4 kv = *(const float4*)&Ks[s][j];   // broadcast
                    d0 += q[j] * kv.x; d1 += q[j + 1] * kv.y;
                    d2 += q[j + 2] * kv.z; d3 += q[j + 3] * kv.w;
                }
                const bool valid = (s < s_cnt) && (s0 + s <= t);
                x[c] = valid ? (d0 + d1 + d2 + d3) * scale : -INFINITY;
            }
            float cm = mi;
            #pragma unroll
            for (int c = 0; c < 8; c++) cm = fmaxf(cm, x[c]);
            if (cm > mi) {
                float f = __expf(mi - cm);   // expf(-inf)=0 on first update
                li *= f;
                #pragma unroll
                for (int e = 0; e < EE; e++) o[e] *= f;
                mi = cm;
            }
            #pragma unroll
            for (int c = 0; c < 8; c++) {
                const int s = sc + c;
                float p = __expf(x[c] - mi);  // mi finite after first chunk; masked -> 0
                li += p;
                #pragma unroll
                for (int j = 0; j < EE; j += 4) {
                    float4 v = *(const float4*)&Vs[s][j];    // broadcast
                    o[j]     += p * v.x; o[j + 1] += p * v.y;
                    o[j + 2] += p * v.z; o[j + 3] += p * v.w;
                }
            }
        }
    }

    const float inv = 1.0f / li;   // li > 0: key s=0 always valid (causal, len>=1)
    float* op = &out[(((size_t)b * TT + t) * MM + m) * PP + h * EE];
    #pragma unroll
    for (int j = 0; j < EE; j += 4) {
        float4 v = make_float4(o[j] * inv, o[j + 1] * inv, o[j + 2] * inv, o[j + 3] * inv);
        *(float4*)&op[j] = v;
    }
}

// ---------------------------------------------------------------------------
// Entry point. Input order per metadata:
// 0 inp, 1 pos, 2 mask, 3 Wq, 4 Bq, 5 Wk, 6 Bk, 7 Wv, 8 Bv,
// 9 Wq_t, 10 Bq_t, 11 Wk_t, 12 Bk_t
// ---------------------------------------------------------------------------
extern "C" void kernel_launch(void* const* d_in, const int* in_sizes, int n_in,
                              void* d_out, int out_size) {
    const float* inp  = (const float*)d_in[0];
    const float* pos  = (const float*)d_in[1];
    const unsigned char* mask = (const unsigned char*)d_in[2];
    const float* Wq   = (const float*)d_in[3];
    const float* Bq   = (const float*)d_in[4];
    const float* Wk   = (const float*)d_in[5];
    const float* Bk   = (const float*)d_in[6];
    const float* Wv   = (const float*)d_in[7];
    const float* Bv_  = (const float*)d_in[8];
    const float* Wqt  = (const float*)d_in[9];
    const float* Bqt  = (const float*)d_in[10];
    const float* Wkt  = (const float*)d_in[11];
    const float* Bkt  = (const float*)d_in[12];
    float* out = (float*)d_out;

    lengths_kernel<<<1, TT>>>(mask);
    proj_kernel<<<dim3(MM, (BB * TT) / 32), 128>>>(
        inp, pos, Wq, Bq, Wk, Bk, Wv, Bv_, Wqt, Bqt, Wkt, Bkt);
    attn_kernel<<<dim3(TT / 128, HH, BB * MM), 128>>>(out);
}

// round 3
// speedup vs baseline: 1.0664x; 1.0664x over previous
#include <cuda_runtime.h>
#include <math.h>

// Problem constants
#define BB 4
#define TT 512
#define MM 16
#define DD 128
#define PP 128
#define HH 4
#define EE 32           // head dim
#define TWOE 64         // concat(q, q_t) head dim

typedef unsigned long long u64;

// ---- packed f32x2 helpers (Blackwell FFMA2 path; only reachable via PTX) ----
__device__ __forceinline__ u64 ffma2(u64 a, u64 b, u64 c) {
    u64 d; asm("fma.rn.f32x2 %0, %1, %2, %3;" : "=l"(d) : "l"(a), "l"(b), "l"(c));
    return d;
}
__device__ __forceinline__ u64 fadd2(u64 a, u64 b) {
    u64 d; asm("add.rn.f32x2 %0, %1, %2;" : "=l"(d) : "l"(a), "l"(b));
    return d;
}
__device__ __forceinline__ u64 fmul2(u64 a, u64 b) {
    u64 d; asm("mul.rn.f32x2 %0, %1, %2;" : "=l"(d) : "l"(a), "l"(b));
    return d;
}
__device__ __forceinline__ u64 pack2(float x, float y) {
    u64 d; asm("mov.b64 %0, {%1, %2};" : "=l"(d) : "f"(x), "f"(y));
    return d;
}
__device__ __forceinline__ float2 unpack2(u64 v) {
    float2 r; asm("mov.b64 {%0, %1}, %2;" : "=f"(r.x), "=f"(r.y) : "l"(v));
    return r;
}

// Scratch (allowed: __device__ globals, no runtime alloc)
__device__ float g_QC[(size_t)BB * MM * HH * TT * TWOE];  // [b][m][h][t][64] : q | q_t
__device__ float g_KC[(size_t)BB * MM * HH * TT * TWOE];  // [b][m][h][t][64] : k | k_t
__device__ float g_V [(size_t)BB * MM * HH * TT * EE];    // [b][m][h][t][32]
__device__ int   g_len[BB];

// ---------------------------------------------------------------------------
// K0: per-batch lengths from mask (dtype-robust: bool/int32/float32).
// ---------------------------------------------------------------------------
__global__ void lengths_kernel(const unsigned char* __restrict__ mask) {
    __shared__ int cnt;
    int tid = threadIdx.x;  // 512 threads
    unsigned char b0 = mask[0], b1 = mask[1];
    bool one_byte = (b0 == 1 && b1 == 1);
    for (int b = 0; b < BB; b++) {
        if (tid == 0) cnt = 0;
        __syncthreads();
        size_t ei = ((size_t)b * TT + tid) * MM;
        bool v;
        if (one_byte) {
            v = mask[ei] != 0;
        } else {
            const unsigned int* m32 = (const unsigned int*)mask;
            v = m32[ei] != 0u;
        }
        unsigned bal = __ballot_sync(0xffffffffu, v);
        if ((tid & 31) == 0) atomicAdd(&cnt, __popc(bal));
        __syncthreads();
        if (tid == 0) g_len[b] = cnt;
        __syncthreads();
    }
}

// ---------------------------------------------------------------------------
// K1: projections with packed FFMA2. Block = (m, 32 bt rows) x 128 p, K=128.
// ---------------------------------------------------------------------------
__global__ void __launch_bounds__(128) proj_kernel(
    const float* __restrict__ inp, const float* __restrict__ pos,
    const float* __restrict__ wq, const float* __restrict__ bq,
    const float* __restrict__ wk, const float* __restrict__ bk,
    const float* __restrict__ wv, const float* __restrict__ bv,
    const float* __restrict__ wqt, const float* __restrict__ bqt,
    const float* __restrict__ wkt, const float* __restrict__ bkt)
{
    __shared__ float Xs[32][DD];   // inp rows   (16 KB)
    __shared__ float Ps[32][DD];   // pos rows   (16 KB)
    __shared__ float Ws[32][PP];   // W chunk transposed [d_local][p] (16 KB)

    const int m   = blockIdx.x;
    const int bt0 = blockIdx.y * 32;
    const int tid = threadIdx.x;   // 128

    #pragma unroll
    for (int it = 0; it < 8; it++) {
        int idx = it * 128 + tid;       // float4 index, 1024 per tile
        int r = idx >> 5, c4 = idx & 31;
        int bt = bt0 + r;
        float4 vx = *(const float4*)&inp[((size_t)bt * MM + m) * DD + c4 * 4];
        *(float4*)&Xs[r][c4 * 4] = vx;
        float4 vp = *(const float4*)&pos[(size_t)bt * DD + c4 * 4];
        *(float4*)&Ps[r][c4 * 4] = vp;
    }

    const int c0 = (tid & 31) * 4;   // 4 output columns (p)
    const int r0 = (tid >> 5) * 8;   // 8 rows
    const int h  = c0 >> 5;
    const int e0 = c0 & 31;

    const float* Wm[5] = {wq, wk, wv, wqt, wkt};
    const float* Bm[5] = {bq, bk, bv, bqt, bkt};

    #pragma unroll 1
    for (int mat = 0; mat < 5; mat++) {
        const float* W = Wm[mat] + (size_t)m * PP * DD;
        const bool usePos = (mat >= 3);
        u64 accp[8][2];
        #pragma unroll
        for (int r = 0; r < 8; r++) { accp[r][0] = 0ull; accp[r][1] = 0ull; }

        #pragma unroll 1
        for (int dc = 0; dc < 4; dc++) {            // 4 chunks of 32 d
            __syncthreads();
            #pragma unroll
            for (int it = 0; it < 8; it++) {
                int idx = it * 128 + tid;           // 1024 float4s
                int p = idx >> 3, c4 = idx & 7;
                float4 w4 = *(const float4*)&W[(size_t)p * DD + dc * 32 + c4 * 4];
                Ws[c4 * 4 + 0][p] = w4.x;
                Ws[c4 * 4 + 1][p] = w4.y;
                Ws[c4 * 4 + 2][p] = w4.z;
                Ws[c4 * 4 + 3][p] = w4.w;
            }
            __syncthreads();
            const float (*X)[DD] = usePos ? Ps : Xs;
            #pragma unroll 8
            for (int dd = 0; dd < 32; dd++) {
                int d = dc * 32 + dd;
                float4 w = *(const float4*)&Ws[dd][c0];
                u64 w01 = pack2(w.x, w.y);
                u64 w23 = pack2(w.z, w.w);
                #pragma unroll
                for (int r = 0; r < 8; r++) {
                    float x = X[r0 + r][d];
                    u64 xp = pack2(x, x);
                    accp[r][0] = ffma2(xp, w01, accp[r][0]);
                    accp[r][1] = ffma2(xp, w23, accp[r][1]);
                }
            }
        }

        float bias[4];
        #pragma unroll
        for (int j = 0; j < 4; j++) bias[j] = Bm[mat][m * PP + c0 + j];

        #pragma unroll
        for (int r = 0; r < 8; r++) {
            int bt = bt0 + r0 + r;
            int b = bt >> 9, t = bt & (TT - 1);
            size_t row = (((size_t)(b * MM + m) * HH + h) * TT + t);
            float2 a0 = unpack2(accp[r][0]);
            float2 a1 = unpack2(accp[r][1]);
            float4 v = make_float4(a0.x + bias[0], a0.y + bias[1],
                                   a1.x + bias[2], a1.y + bias[3]);
            switch (mat) {
                case 0: *(float4*)&g_QC[row * TWOE + e0]      = v; break;
                case 1: *(float4*)&g_KC[row * TWOE + e0]      = v; break;
                case 2: *(float4*)&g_V [row * EE   + e0]      = v; break;
                case 3: *(float4*)&g_QC[row * TWOE + 32 + e0] = v; break;
                case 4: *(float4*)&g_KC[row * TWOE + 32 + e0] = v; break;
            }
        }
    }
}

// ---------------------------------------------------------------------------
// K2: flash attention with packed FFMA2 + per-warp causal bound.
// Block = (b,m,h, 128-query tile). One thread per query; q row (32 f32x2
// pairs) in registers; K/V tiles in smem as u64 pairs (reads warp-broadcast).
// ---------------------------------------------------------------------------
__global__ void __launch_bounds__(128) attn_kernel(float* __restrict__ out) {
    __shared__ u64 Ks[128][TWOE / 2];  // 32 KB  (32 pairs per key row)
    __shared__ u64 Vs[128][EE / 2];    // 16 KB  (16 pairs)

    const int qt  = blockIdx.x;            // query tile 0..3
    const int h   = blockIdx.y;
    const int bm  = blockIdx.z;
    const int b   = bm / MM, m = bm % MM;
    const int tid = threadIdx.x;           // 128
    const int t   = qt * 128 + tid;
    const int wmax = t | 31;               // warp-uniform max query index
    const float scale = 0.08838834764831845f;  // 1/(2*sqrt(32))

    const size_t head = ((size_t)(b * MM + m) * HH + h) * TT;
    const u64* KbaseU = (const u64*)&g_KC[head * TWOE];   // 32 u64 per row
    const u64* VbaseU = (const u64*)&g_V [head * EE];     // 16 u64 per row

    u64 q2[TWOE / 2];
    {
        const ulonglong2* qc = (const ulonglong2*)&g_QC[(head + t) * TWOE];
        #pragma unroll
        for (int j = 0; j < TWOE / 4; j++) {
            ulonglong2 v = qc[j];
            q2[j * 2] = v.x; q2[j * 2 + 1] = v.y;
        }
    }

    const int len = g_len[b];
    float mi = -INFINITY, li = 0.f;
    u64 o2[EE / 2];
    #pragma unroll
    for (int e = 0; e < EE / 2; e++) o2[e] = 0ull;

    int s_hi = qt * 128 + 127;
    if (s_hi > len - 1) s_hi = len - 1;
    const int ntiles = s_hi / 128 + 1;

    for (int ktile = 0; ktile < ntiles; ktile++) {
        const int s0 = ktile * 128;
        __syncthreads();
        #pragma unroll
        for (int it = 0; it < 16; it++) {           // K tile: 2048 x 16B
            int idx = it * 128 + tid;
            int r = idx >> 4, c = idx & 15;
            *(ulonglong2*)&Ks[r][c * 2] =
                *(const ulonglong2*)&KbaseU[(size_t)(s0 + r) * (TWOE / 2) + c * 2];
        }
        #pragma unroll
        for (int it = 0; it < 8; it++) {            // V tile: 1024 x 16B
            int idx = it * 128 + tid;
            int r = idx >> 3, c = idx & 7;
            *(ulonglong2*)&Vs[r][c * 2] =
                *(const ulonglong2*)&VbaseU[(size_t)(s0 + r) * (EE / 2) + c * 2];
        }
        __syncthreads();

        int s_cnt = len - s0; if (s_cnt > 128) s_cnt = 128;   // tile valid-count
        int s_cnt_w = wmax + 1 - s0;                          // per-warp causal bound
        if (s_cnt_w > s_cnt) s_cnt_w = s_cnt;

        for (int sc = 0; sc < s_cnt_w; sc += 8) {
            float x[8];
            #pragma unroll
            for (int c = 0; c < 8; c++) {
                const int s = sc + c;
                u64 a0 = 0ull, a1 = 0ull, a2 = 0ull, a3 = 0ull;
                #pragma unroll
                for (int j = 0; j < TWOE / 2; j += 4) {
                    a0 = ffma2(q2[j],     Ks[s][j],     a0);
                    a1 = ffma2(q2[j + 1], Ks[s][j + 1], a1);
                    a2 = ffma2(q2[j + 2], Ks[s][j + 2], a2);
                    a3 = ffma2(q2[j + 3], Ks[s][j + 3], a3);
                }
                a0 = fadd2(a0, a1);
                a2 = fadd2(a2, a3);
                a0 = fadd2(a0, a2);
                float2 f = unpack2(a0);
                const bool valid = (s < s_cnt) && (s0 + s <= t);
                x[c] = valid ? (f.x + f.y) * scale : -INFINITY;
            }
            float cm = mi;
            #pragma unroll
            for (int c = 0; c < 8; c++) cm = fmaxf(cm, x[c]);
            if (cm > mi) {
                float f = __expf(mi - cm);   // expf(-inf)=0 on first update
                li *= f;
                u64 fp = pack2(f, f);
                #pragma unroll
                for (int e = 0; e < EE / 2; e++) o2[e] = fmul2(o2[e], fp);
                mi = cm;
            }
            #pragma unroll
            for (int c = 0; c < 8; c++) {
                const int s = sc + c;
                float p = __expf(x[c] - mi);  // masked -> 0
                li += p;
                u64 pp = pack2(p, p);
                #pragma unroll
                for (int j = 0; j < EE / 2; j++)
                    o2[j] = ffma2(pp, Vs[s][j], o2[j]);
            }
        }
    }

    const float inv = 1.0f / li;   // li > 0: key s=0 always valid
    float* op = &out[(((size_t)b * TT + t) * MM + m) * PP + h * EE];
    #pragma unroll
    for (int j = 0; j < EE / 2; j += 2) {
        float2 f0 = unpack2(o2[j]);
        float2 f1 = unpack2(o2[j + 1]);
        float4 v = make_float4(f0.x * inv, f0.y * inv, f1.x * inv, f1.y * inv);
        *(float4*)&op[j * 2] = v;
    }
}

// ---------------------------------------------------------------------------
// Entry point. Input order per metadata:
// 0 inp, 1 pos, 2 mask, 3 Wq, 4 Bq, 5 Wk, 6 Bk, 7 Wv, 8 Bv,
// 9 Wq_t, 10 Bq_t, 11 Wk_t, 12 Bk_t
// ---------------------------------------------------------------------------
extern "C" void kernel_launch(void* const* d_in, const int* in_sizes, int n_in,
                              void* d_out, int out_size) {
    const float* inp  = (const float*)d_in[0];
    const float* pos  = (const float*)d_in[1];
    const unsigned char* mask = (const unsigned char*)d_in[2];
    const float* Wq   = (const float*)d_in[3];
    const float* Bq   = (const float*)d_in[4];
    const float* Wk   = (const float*)d_in[5];
    const float* Bk   = (const float*)d_in[6];
    const float* Wv   = (const float*)d_in[7];
    const float* Bv_  = (const float*)d_in[8];
    const float* Wqt  = (const float*)d_in[9];
    const float* Bqt  = (const float*)d_in[10];
    const float* Wkt  = (const float*)d_in[11];
    const float* Bkt  = (const float*)d_in[12];
    float* out = (float*)d_out;

    lengths_kernel<<<1, TT>>>(mask);
    proj_kernel<<<dim3(MM, (BB * TT) / 32), 128>>>(
        inp, pos, Wq, Bq, Wk, Bk, Wv, Bv_, Wqt, Bqt, Wkt, Bkt);
    attn_kernel<<<dim3(TT / 128, HH, BB * MM), 128>>>(out);
}

// round 4
// speedup vs baseline: 1.0950x; 1.0268x over previous
#include <cuda_runtime.h>
#include <math.h>

// Problem constants
#define BB 4
#define TT 512
#define MM 16
#define DD 128
#define PP 128
#define HH 4
#define EE 32           // head dim
#define TWOE 64         // concat(q, q_t) head dim

typedef unsigned long long u64;

// ---- packed f32x2 helpers (Blackwell FFMA2 path; only reachable via PTX) ----
__device__ __forceinline__ u64 ffma2(u64 a, u64 b, u64 c) {
    u64 d; asm("fma.rn.f32x2 %0, %1, %2, %3;" : "=l"(d) : "l"(a), "l"(b), "l"(c));
    return d;
}
__device__ __forceinline__ u64 fadd2(u64 a, u64 b) {
    u64 d; asm("add.rn.f32x2 %0, %1, %2;" : "=l"(d) : "l"(a), "l"(b));
    return d;
}
__device__ __forceinline__ u64 fmul2(u64 a, u64 b) {
    u64 d; asm("mul.rn.f32x2 %0, %1, %2;" : "=l"(d) : "l"(a), "l"(b));
    return d;
}
__device__ __forceinline__ u64 pack2(float x, float y) {
    u64 d; asm("mov.b64 %0, {%1, %2};" : "=l"(d) : "f"(x), "f"(y));
    return d;
}
__device__ __forceinline__ float2 unpack2(u64 v) {
    float2 r; asm("mov.b64 {%0, %1}, %2;" : "=f"(r.x), "=f"(r.y) : "l"(v));
    return r;
}

// Scratch (allowed: __device__ globals, no runtime alloc)
__device__ float g_QC[(size_t)BB * MM * HH * TT * TWOE];  // [b][m][h][t][64] : q | q_t
__device__ float g_KC[(size_t)BB * MM * HH * TT * TWOE];  // [b][m][h][t][64] : k | k_t
__device__ float g_V [(size_t)BB * MM * HH * TT * EE];    // [b][m][h][t][32]
__device__ int   g_len[BB];

// ---------------------------------------------------------------------------
// K0: per-batch lengths from mask (dtype-robust: bool/int32/float32).
// ---------------------------------------------------------------------------
__global__ void lengths_kernel(const unsigned char* __restrict__ mask) {
    __shared__ int cnt;
    int tid = threadIdx.x;  // 512 threads
    unsigned char b0 = mask[0], b1 = mask[1];
    bool one_byte = (b0 == 1 && b1 == 1);
    for (int b = 0; b < BB; b++) {
        if (tid == 0) cnt = 0;
        __syncthreads();
        size_t ei = ((size_t)b * TT + tid) * MM;
        bool v;
        if (one_byte) {
            v = mask[ei] != 0;
        } else {
            const unsigned int* m32 = (const unsigned int*)mask;
            v = m32[ei] != 0u;
        }
        unsigned bal = __ballot_sync(0xffffffffu, v);
        if ((tid & 31) == 0) atomicAdd(&cnt, __popc(bal));
        __syncthreads();
        if (tid == 0) g_len[b] = cnt;
        __syncthreads();
    }
}

// ---------------------------------------------------------------------------
// K1: projections with packed FFMA2. Block = (m, 32 bt rows) x 128 p, K=128.
// ---------------------------------------------------------------------------
__global__ void __launch_bounds__(128) proj_kernel(
    const float* __restrict__ inp, const float* __restrict__ pos,
    const float* __restrict__ wq, const float* __restrict__ bq,
    const float* __restrict__ wk, const float* __restrict__ bk,
    const float* __restrict__ wv, const float* __restrict__ bv,
    const float* __restrict__ wqt, const float* __restrict__ bqt,
    const float* __restrict__ wkt, const float* __restrict__ bkt)
{
    __shared__ float Xs[32][DD];   // inp rows   (16 KB)
    __shared__ float Ps[32][DD];   // pos rows   (16 KB)
    __shared__ float Ws[32][PP];   // W chunk transposed [d_local][p] (16 KB)

    const int m   = blockIdx.x;
    const int bt0 = blockIdx.y * 32;
    const int tid = threadIdx.x;   // 128

    #pragma unroll
    for (int it = 0; it < 8; it++) {
        int idx = it * 128 + tid;       // float4 index, 1024 per tile
        int r = idx >> 5, c4 = idx & 31;
        int bt = bt0 + r;
        float4 vx = *(const float4*)&inp[((size_t)bt * MM + m) * DD + c4 * 4];
        *(float4*)&Xs[r][c4 * 4] = vx;
        float4 vp = *(const float4*)&pos[(size_t)bt * DD + c4 * 4];
        *(float4*)&Ps[r][c4 * 4] = vp;
    }

    const int c0 = (tid & 31) * 4;   // 4 output columns (p)
    const int r0 = (tid >> 5) * 8;   // 8 rows
    const int h  = c0 >> 5;
    const int e0 = c0 & 31;

    const float* Wm[5] = {wq, wk, wv, wqt, wkt};
    const float* Bm[5] = {bq, bk, bv, bqt, bkt};

    #pragma unroll 1
    for (int mat = 0; mat < 5; mat++) {
        const float* W = Wm[mat] + (size_t)m * PP * DD;
        const bool usePos = (mat >= 3);
        u64 accp[8][2];
        #pragma unroll
        for (int r = 0; r < 8; r++) { accp[r][0] = 0ull; accp[r][1] = 0ull; }

        #pragma unroll 1
        for (int dc = 0; dc < 4; dc++) {            // 4 chunks of 32 d
            __syncthreads();
            #pragma unroll
            for (int it = 0; it < 8; it++) {
                int idx = it * 128 + tid;           // 1024 float4s
                int p = idx >> 3, c4 = idx & 7;
                float4 w4 = *(const float4*)&W[(size_t)p * DD + dc * 32 + c4 * 4];
                Ws[c4 * 4 + 0][p] = w4.x;
                Ws[c4 * 4 + 1][p] = w4.y;
                Ws[c4 * 4 + 2][p] = w4.z;
                Ws[c4 * 4 + 3][p] = w4.w;
            }
            __syncthreads();
            const float (*X)[DD] = usePos ? Ps : Xs;
            #pragma unroll 8
            for (int dd = 0; dd < 32; dd++) {
                int d = dc * 32 + dd;
                float4 w = *(const float4*)&Ws[dd][c0];
                u64 w01 = pack2(w.x, w.y);
                u64 w23 = pack2(w.z, w.w);
                #pragma unroll
                for (int r = 0; r < 8; r++) {
                    float x = X[r0 + r][d];
                    u64 xp = pack2(x, x);
                    accp[r][0] = ffma2(xp, w01, accp[r][0]);
                    accp[r][1] = ffma2(xp, w23, accp[r][1]);
                }
            }
        }

        float bias[4];
        #pragma unroll
        for (int j = 0; j < 4; j++) bias[j] = Bm[mat][m * PP + c0 + j];

        #pragma unroll
        for (int r = 0; r < 8; r++) {
            int bt = bt0 + r0 + r;
            int b = bt >> 9, t = bt & (TT - 1);
            size_t row = (((size_t)(b * MM + m) * HH + h) * TT + t);
            float2 a0 = unpack2(accp[r][0]);
            float2 a1 = unpack2(accp[r][1]);
            float4 v = make_float4(a0.x + bias[0], a0.y + bias[1],
                                   a1.x + bias[2], a1.y + bias[3]);
            switch (mat) {
                case 0: *(float4*)&g_QC[row * TWOE + e0]      = v; break;
                case 1: *(float4*)&g_KC[row * TWOE + e0]      = v; break;
                case 2: *(float4*)&g_V [row * EE   + e0]      = v; break;
                case 3: *(float4*)&g_QC[row * TWOE + 32 + e0] = v; break;
                case 4: *(float4*)&g_KC[row * TWOE + 32 + e0] = v; break;
            }
        }
    }
}

// ---------------------------------------------------------------------------
// K2: flash attention with packed FFMA2 + per-warp causal bound.
// Block = (b,m,h, 128-query tile). One thread per query; q row (32 f32x2
// pairs) in registers; K/V tiles in smem as u64 pairs (reads warp-broadcast).
// ---------------------------------------------------------------------------
__global__ void __launch_bounds__(128) attn_kernel(float* __restrict__ out) {
    __shared__ u64 Ks[128][TWOE / 2];  // 32 KB  (32 pairs per key row)
    __shared__ u64 Vs[128][EE / 2];    // 16 KB  (16 pairs)

    const int qt  = blockIdx.x;            // query tile 0..3
    const int h   = blockIdx.y;
    const int bm  = blockIdx.z;
    const int b   = bm / MM, m = bm % MM;
    const int tid = threadIdx.x;           // 128
    const int t   = qt * 128 + tid;
    const int wmax = t | 31;               // warp-uniform max query index
    const float scale = 0.08838834764831845f;  // 1/(2*sqrt(32))

    const size_t head = ((size_t)(b * MM + m) * HH + h) * TT;
    const u64* KbaseU = (const u64*)&g_KC[head * TWOE];   // 32 u64 per row
    const u64* VbaseU = (const u64*)&g_V [head * EE];     // 16 u64 per row

    u64 q2[TWOE / 2];
    {
        const ulonglong2* qc = (const ulonglong2*)&g_QC[(head + t) * TWOE];
        #pragma unroll
        for (int j = 0; j < TWOE / 4; j++) {
            ulonglong2 v = qc[j];
            q2[j * 2] = v.x; q2[j * 2 + 1] = v.y;
        }
    }

    const int len = g_len[b];
    float mi = -INFINITY, li = 0.f;
    u64 o2[EE / 2];
    #pragma unroll
    for (int e = 0; e < EE / 2; e++) o2[e] = 0ull;

    int s_hi = qt * 128 + 127;
    if (s_hi > len - 1) s_hi = len - 1;
    const int ntiles = s_hi / 128 + 1;

    for (int ktile = 0; ktile < ntiles; ktile++) {
        const int s0 = ktile * 128;
        __syncthreads();
        #pragma unroll
        for (int it = 0; it < 16; it++) {           // K tile: 2048 x 16B
            int idx = it * 128 + tid;
            int r = idx >> 4, c = idx & 15;
            *(ulonglong2*)&Ks[r][c * 2] =
                *(const ulonglong2*)&KbaseU[(size_t)(s0 + r) * (TWOE / 2) + c * 2];
        }
        #pragma unroll
        for (int it = 0; it < 8; it++) {            // V tile: 1024 x 16B
            int idx = it * 128 + tid;
            int r = idx >> 3, c = idx & 7;
            *(ulonglong2*)&Vs[r][c * 2] =
                *(const ulonglong2*)&VbaseU[(size_t)(s0 + r) * (EE / 2) + c * 2];
        }
        __syncthreads();

        int s_cnt = len - s0; if (s_cnt > 128) s_cnt = 128;   // tile valid-count
        int s_cnt_w = wmax + 1 - s0;                          // per-warp causal bound
        if (s_cnt_w > s_cnt) s_cnt_w = s_cnt;

        for (int sc = 0; sc < s_cnt_w; sc += 8) {
            float x[8];
            #pragma unroll
            for (int c = 0; c < 8; c++) {
                const int s = sc + c;
                u64 a0 = 0ull, a1 = 0ull, a2 = 0ull, a3 = 0ull;
                #pragma unroll
                for (int j = 0; j < TWOE / 2; j += 4) {
                    a0 = ffma2(q2[j],     Ks[s][j],     a0);
                    a1 = ffma2(q2[j + 1], Ks[s][j + 1], a1);
                    a2 = ffma2(q2[j + 2], Ks[s][j + 2], a2);
                    a3 = ffma2(q2[j + 3], Ks[s][j + 3], a3);
                }
                a0 = fadd2(a0, a1);
                a2 = fadd2(a2, a3);
                a0 = fadd2(a0, a2);
                float2 f = unpack2(a0);
                const bool valid = (s < s_cnt) && (s0 + s <= t);
                x[c] = valid ? (f.x + f.y) * scale : -INFINITY;
            }
            float cm = mi;
            #pragma unroll
            for (int c = 0; c < 8; c++) cm = fmaxf(cm, x[c]);
            if (cm > mi) {
                float f = __expf(mi - cm);   // expf(-inf)=0 on first update
                li *= f;
                u64 fp = pack2(f, f);
                #pragma unroll
                for (int e = 0; e < EE / 2; e++) o2[e] = fmul2(o2[e], fp);
                mi = cm;
            }
            #pragma unroll
            for (int c = 0; c < 8; c++) {
                const int s = sc + c;
                float p = __expf(x[c] - mi);  // masked -> 0
                li += p;
                u64 pp = pack2(p, p);
                #pragma unroll
                for (int j = 0; j < EE / 2; j++)
                    o2[j] = ffma2(pp, Vs[s][j], o2[j]);
            }
        }
    }

    const float inv = 1.0f / li;   // li > 0: key s=0 always valid
    float* op = &out[(((size_t)b * TT + t) * MM + m) * PP + h * EE];
    #pragma unroll
    for (int j = 0; j < EE / 2; j += 2) {
        float2 f0 = unpack2(o2[j]);
        float2 f1 = unpack2(o2[j + 1]);
        float4 v = make_float4(f0.x * inv, f0.y * inv, f1.x * inv, f1.y * inv);
        *(float4*)&op[j * 2] = v;
    }
}

// ---------------------------------------------------------------------------
// Entry point. Input order per metadata:
// 0 inp, 1 pos, 2 mask, 3 Wq, 4 Bq, 5 Wk, 6 Bk, 7 Wv, 8 Bv,
// 9 Wq_t, 10 Bq_t, 11 Wk_t, 12 Bk_t
// ---------------------------------------------------------------------------
extern "C" void kernel_launch(void* const* d_in, const int* in_sizes, int n_in,
                              void* d_out, int out_size) {
    const float* inp  = (const float*)d_in[0];
    const float* pos  = (const float*)d_in[1];
    const unsigned char* mask = (const unsigned char*)d_in[2];
    const float* Wq   = (const float*)d_in[3];
    const float* Bq   = (const float*)d_in[4];
    const float* Wk   = (const float*)d_in[5];
    const float* Bk   = (const float*)d_in[6];
    const float* Wv   = (const float*)d_in[7];
    const float* Bv_  = (const float*)d_in[8];
    const float* Wqt  = (const float*)d_in[9];
    const float* Bqt  = (const float*)d_in[10];
    const float* Wkt  = (const float*)d_in[11];
    const float* Bkt  = (const float*)d_in[12];
    float* out = (float*)d_out;

    lengths_kernel<<<1, TT>>>(mask);
    proj_kernel<<<dim3(MM, (BB * TT) / 32), 128>>>(
        inp, pos, Wq, Bq, Wk, Bk, Wv, Bv_, Wqt, Bqt, Wkt, Bkt);
    attn_kernel<<<dim3(TT / 128, HH, BB * MM), 128>>>(out);
}